// round 1
// baseline (speedup 1.0000x reference)
#include <cuda_runtime.h>
#include <cuda_bf16.h>
#include <math.h>

// CannyFilter: B=32, C=3, H=W=512.
// Fully fused single-kernel implementation.
//
// Exact reductions used (verified against the reference math):
//  - gaussian & sobel weights identical per channel, pipeline linear up to sqrt
//    => sum channels first, run single-channel.
//  - nms_w rows identical across the 8 directional channels
//    => thin = conv(conv(mag, sum_k dir_k), nms_row).  D and R are computed
//       from the input tensors, not hardcoded.
//  - Every intermediate's zero padding reproduced exactly via in-domain masks.

#define IMG_H 512
#define IMG_W 512
#define TS 32

#define I_W 40   // img tile   (halo 4)
#define B_W 38   // blur tile  (halo 3)
#define M_W 36   // mag tile   (halo 2)
#define S_W 34   // S tile     (halo 1)

__global__ __launch_bounds__(256)
void canny_fused_kernel(const float* __restrict__ img,
                        const float* __restrict__ gauss_w,
                        const float* __restrict__ sobx_w,
                        const float* __restrict__ soby_w,
                        const float* __restrict__ dir_w,
                        const float* __restrict__ nms_w,
                        float* __restrict__ out)
{
    __shared__ float sI[I_W * I_W];
    __shared__ float sB[B_W * B_W];
    __shared__ float sM[M_W * M_W];
    __shared__ float sS[S_W * S_W];
    __shared__ float wG[9], wX[9], wY[9], wD[9], wR[9];

    const int tid = threadIdx.x;

    // Load / reduce the tiny weight tensors once per block.
    if (tid < 9) {
        wG[tid] = gauss_w[tid];       // first channel; all channels identical
        wX[tid] = sobx_w[tid];
        wY[tid] = soby_w[tid];
        float d = 0.f;
        #pragma unroll
        for (int k = 0; k < 8; k++) d += dir_w[k * 9 + tid];   // sum of 8 dir kernels
        wD[tid] = d;
        wR[tid] = nms_w[tid];         // nms row 0 (all 8 rows identical)
    }

    const int X0 = blockIdx.x * TS;
    const int Y0 = blockIdx.y * TS;
    const int b  = blockIdx.z;
    const float* im = img + (size_t)b * 3 * IMG_H * IMG_W;

    // ---- Stage 0: load img tile with halo 4, summing the 3 channels ----
    for (int i = tid; i < I_W * I_W; i += 256) {
        const int r = i / I_W, c = i % I_W;
        const int gy = Y0 + r - 4, gx = X0 + c - 4;
        float v = 0.f;
        if ((unsigned)gy < IMG_H && (unsigned)gx < IMG_W) {
            const int off = gy * IMG_W + gx;
            v = im[off] + im[IMG_H * IMG_W + off] + im[2 * IMG_H * IMG_W + off];
        }
        sI[i] = v;
    }
    __syncthreads();

    // ---- Stage 1: gaussian blur (zero-pad of img already in sI) ----
    for (int i = tid; i < B_W * B_W; i += 256) {
        const int r = i / B_W, c = i % B_W;
        const int gy = Y0 + r - 3, gx = X0 + c - 3;
        float v = 0.f;
        if ((unsigned)gy < IMG_H && (unsigned)gx < IMG_W) {
            #pragma unroll
            for (int ky = 0; ky < 3; ky++)
                #pragma unroll
                for (int kx = 0; kx < 3; kx++)
                    v = fmaf(wG[ky * 3 + kx], sI[(r + ky) * I_W + (c + kx)], v);
        }
        sB[i] = v;   // 0 outside domain == blurred's zero pad for sobel
    }
    __syncthreads();

    // ---- Stage 2: sobel x/y (shared loads), channel-mean, magnitude ----
    for (int i = tid; i < M_W * M_W; i += 256) {
        const int r = i / M_W, c = i % M_W;
        const int gy = Y0 + r - 2, gx = X0 + c - 2;
        float v = 0.f;
        if ((unsigned)gy < IMG_H && (unsigned)gx < IMG_W) {
            float ax = 0.f, ay = 0.f;
            #pragma unroll
            for (int ky = 0; ky < 3; ky++)
                #pragma unroll
                for (int kx = 0; kx < 3; kx++) {
                    const float t = sB[(r + ky) * B_W + (c + kx)];
                    ax = fmaf(wX[ky * 3 + kx], t, ax);
                    ay = fmaf(wY[ky * 3 + kx], t, ay);
                }
            v = sqrtf(ax * ax + ay * ay) * (1.f / 3.f);  // /C folded in
        }
        sM[i] = v;
    }
    __syncthreads();

    // ---- Stage 3: S = conv(mag, D) ----
    for (int i = tid; i < S_W * S_W; i += 256) {
        const int r = i / S_W, c = i % S_W;
        const int gy = Y0 + r - 1, gx = X0 + c - 1;
        float v = 0.f;
        if ((unsigned)gy < IMG_H && (unsigned)gx < IMG_W) {
            #pragma unroll
            for (int ky = 0; ky < 3; ky++)
                #pragma unroll
                for (int kx = 0; kx < 3; kx++)
                    v = fmaf(wD[ky * 3 + kx], sM[(r + ky) * M_W + (c + kx)], v);
        }
        sS[i] = v;
    }
    __syncthreads();

    // ---- Stage 4: thin = conv(S, R), write output ----
    float* ob = out + (size_t)b * IMG_H * IMG_W;
    for (int i = tid; i < TS * TS; i += 256) {
        const int r = i / TS, c = i % TS;
        float v = 0.f;
        #pragma unroll
        for (int ky = 0; ky < 3; ky++)
            #pragma unroll
            for (int kx = 0; kx < 3; kx++)
                v = fmaf(wR[ky * 3 + kx], sS[(r + ky) * S_W + (c + kx)], v);
        ob[(Y0 + r) * IMG_W + (X0 + c)] = v;
    }
}

extern "C" void kernel_launch(void* const* d_in, const int* in_sizes, int n_in,
                              void* d_out, int out_size)
{
    const float* img     = (const float*)d_in[0];  // (32,3,512,512)
    const float* gauss_w = (const float*)d_in[1];  // (3,1,3,3)
    const float* sobx_w  = (const float*)d_in[2];  // (3,1,3,3)
    const float* soby_w  = (const float*)d_in[3];  // (3,1,3,3)
    const float* dir_w   = (const float*)d_in[4];  // (8,1,3,3)
    const float* nms_w   = (const float*)d_in[5];  // (1,8,3,3)
    float* out = (float*)d_out;                    // (32,1,512,512)

    dim3 grid(IMG_W / TS, IMG_H / TS, 32);
    canny_fused_kernel<<<grid, 256>>>(img, gauss_w, sobx_w, soby_w,
                                      dir_w, nms_w, out);
}

// round 3
// speedup vs baseline: 1.3170x; 1.3170x over previous
#include <cuda_runtime.h>
#include <cuda_bf16.h>
#include <math.h>

// CannyFilter B=32,C=3,H=W=512 — fused, 2-stage interior / 4-stage border.
//
// Exact reductions (all computed from the input tensors at runtime):
//  - per-channel weights identical + linearity up to sqrt => sum channels once.
//  - correlation composition: thin = corr(mag, DR5x5), mag from corr(img, GX5x5/GY5x5),
//    exact wherever intermediates are >=1px inside the image => interior tiles
//    run a branch-free 2-stage path; border tiles run the masked 4-stage path.
//  - all weights staged into __constant__ so FMAs use c[][] operands (no LDS).

#define IMG 512
#define TS 32
#define I_W 40   // img tile  (halo 4)
#define B_W 38   // blur tile (halo 3)  [border path]
#define M_W 36   // mag tile  (halo 2)
#define S_W 34   // S tile    (halo 1)  [border path]

// layout: [0:25) GX, [25:50) GY, [50:75) DR, [75:84) G, [84:93) X,
//         [93:102) Y, [102:111) D, [111:120) R
__constant__ float cW[120];
__device__ float g_wbuf[120];

__global__ void prep_weights(const float* __restrict__ g, const float* __restrict__ sx,
                             const float* __restrict__ sy, const float* __restrict__ dw,
                             const float* __restrict__ nw)
{
    int t = threadIdx.x;
    if (t < 25) {
        int wy = t / 5, wx = t % 5;
        float ax = 0.f, ay = 0.f, ad = 0.f;
        for (int vy = 0; vy < 3; vy++)
            for (int vx = 0; vx < 3; vx++) {
                int uy = wy - vy, ux = wx - vx;
                if (uy >= 0 && uy < 3 && ux >= 0 && ux < 3) {
                    float gg = g[vy * 3 + vx];
                    ax += gg * sx[uy * 3 + ux];
                    ay += gg * sy[uy * 3 + ux];
                    for (int k = 0; k < 8; k++)   // exact per-direction composition
                        ad += dw[k * 9 + vy * 3 + vx] * nw[k * 9 + uy * 3 + ux];
                }
            }
        g_wbuf[t] = ax; g_wbuf[25 + t] = ay; g_wbuf[50 + t] = ad;
    }
    if (t < 9) {
        g_wbuf[75 + t] = g[t];
        g_wbuf[84 + t] = sx[t];
        g_wbuf[93 + t] = sy[t];
        float d = 0.f;
        for (int k = 0; k < 8; k++) d += dw[k * 9 + t];
        g_wbuf[102 + t] = d;
        g_wbuf[111 + t] = nw[t];
    }
}

__global__ __launch_bounds__(256)
void canny_main(const float* __restrict__ img, float* __restrict__ out)
{
    __shared__ float sI[I_W * I_W];
    __shared__ float sB[B_W * B_W];   // interior: reused as 36x36 mag buffer
    __shared__ float sM[M_W * M_W];
    __shared__ float sS[S_W * S_W];

    const int tid = threadIdx.x;
    const int X0 = blockIdx.x * TS, Y0 = blockIdx.y * TS, b = blockIdx.z;
    const float* im = img + (size_t)b * 3 * IMG * IMG;
    float* ob = out + (size_t)b * IMG * IMG;

    const bool interior = (blockIdx.x - 1u < 14u) && (blockIdx.y - 1u < 14u);

    if (interior) {
        // ---- stage 0: load 40x40 img tile, channel-summed, no bounds checks ----
        const int base = (Y0 - 4) * IMG + (X0 - 4);
        // 256 threads, 1600 elems: 6 strips + remainder, row index via small loop
        for (int i = tid; i < I_W * I_W; i += 256) {
            const int r = i / I_W, c = i - r * I_W;
            const int off = base + r * IMG + c;
            sI[i] = __ldg(im + off) + __ldg(im + IMG * IMG + off)
                  + __ldg(im + 2 * IMG * IMG + off);
        }
        __syncthreads();

        // ---- stage A: mag 36x36 via fused 5x5 GX/GY, 6-row register blocking ----
        if (tid < 216) {
            const int col = tid % 36;
            const int r0 = (tid / 36) * 6;
            float accX[6] = {0, 0, 0, 0, 0, 0};
            float accY[6] = {0, 0, 0, 0, 0, 0};
            #pragma unroll
            for (int ir = 0; ir < 10; ir++) {
                float v[5];
                #pragma unroll
                for (int j = 0; j < 5; j++) v[j] = sI[(r0 + ir) * I_W + col + j];
                #pragma unroll
                for (int k = 0; k < 6; k++) {
                    const int w = ir - k;
                    if (w >= 0 && w < 5) {
                        #pragma unroll
                        for (int j = 0; j < 5; j++) {
                            accX[k] = fmaf(cW[w * 5 + j],      v[j], accX[k]);
                            accY[k] = fmaf(cW[25 + w * 5 + j], v[j], accY[k]);
                        }
                    }
                }
            }
            #pragma unroll
            for (int k = 0; k < 6; k++)
                sB[(r0 + k) * M_W + col] =
                    sqrtf(accX[k] * accX[k] + accY[k] * accY[k]) * (1.f / 3.f);
        }
        __syncthreads();

        // ---- stage B: out 32x32 via fused 5x5 DR, 4-row blocking (32x8 map) ----
        {
            const int col = tid & 31;
            const int r0 = (tid >> 5) * 4;
            float acc[4] = {0, 0, 0, 0};
            #pragma unroll
            for (int ir = 0; ir < 8; ir++) {
                float v[5];
                #pragma unroll
                for (int j = 0; j < 5; j++) v[j] = sB[(r0 + ir) * M_W + col + j];
                #pragma unroll
                for (int k = 0; k < 4; k++) {
                    const int w = ir - k;
                    if (w >= 0 && w < 5) {
                        #pragma unroll
                        for (int j = 0; j < 5; j++)
                            acc[k] = fmaf(cW[50 + w * 5 + j], v[j], acc[k]);
                    }
                }
            }
            #pragma unroll
            for (int k = 0; k < 4; k++)
                ob[(Y0 + r0 + k) * IMG + X0 + col] = acc[k];
        }
        return;
    }

    // ================= border path: masked 4-stage (proven exact) =================
    for (int i = tid; i < I_W * I_W; i += 256) {
        const int r = i / I_W, c = i - r * I_W;
        const int gy = Y0 + r - 4, gx = X0 + c - 4;
        float v = 0.f;
        if ((unsigned)gy < IMG && (unsigned)gx < IMG) {
            const int off = gy * IMG + gx;
            v = __ldg(im + off) + __ldg(im + IMG * IMG + off)
              + __ldg(im + 2 * IMG * IMG + off);
        }
        sI[i] = v;
    }
    __syncthreads();

    for (int i = tid; i < B_W * B_W; i += 256) {
        const int r = i / B_W, c = i - r * B_W;
        const int gy = Y0 + r - 3, gx = X0 + c - 3;
        float v = 0.f;
        if ((unsigned)gy < IMG && (unsigned)gx < IMG) {
            #pragma unroll
            for (int ky = 0; ky < 3; ky++)
                #pragma unroll
                for (int kx = 0; kx < 3; kx++)
                    v = fmaf(cW[75 + ky * 3 + kx], sI[(r + ky) * I_W + (c + kx)], v);
        }
        sB[i] = v;
    }
    __syncthreads();

    for (int i = tid; i < M_W * M_W; i += 256) {
        const int r = i / M_W, c = i - r * M_W;
        const int gy = Y0 + r - 2, gx = X0 + c - 2;
        float v = 0.f;
        if ((unsigned)gy < IMG && (unsigned)gx < IMG) {
            float ax = 0.f, ay = 0.f;
            #pragma unroll
            for (int ky = 0; ky < 3; ky++)
                #pragma unroll
                for (int kx = 0; kx < 3; kx++) {
                    const float t = sB[(r + ky) * B_W + (c + kx)];
                    ax = fmaf(cW[84 + ky * 3 + kx], t, ax);
                    ay = fmaf(cW[93 + ky * 3 + kx], t, ay);
                }
            v = sqrtf(ax * ax + ay * ay) * (1.f / 3.f);
        }
        sM[i] = v;
    }
    __syncthreads();

    for (int i = tid; i < S_W * S_W; i += 256) {
        const int r = i / S_W, c = i - r * S_W;
        const int gy = Y0 + r - 1, gx = X0 + c - 1;
        float v = 0.f;
        if ((unsigned)gy < IMG && (unsigned)gx < IMG) {
            #pragma unroll
            for (int ky = 0; ky < 3; ky++)
                #pragma unroll
                for (int kx = 0; kx < 3; kx++)
                    v = fmaf(cW[102 + ky * 3 + kx], sM[(r + ky) * M_W + (c + kx)], v);
        }
        sS[i] = v;
    }
    __syncthreads();

    for (int i = tid; i < TS * TS; i += 256) {
        const int r = i >> 5, c = i & 31;
        float v = 0.f;
        #pragma unroll
        for (int ky = 0; ky < 3; ky++)
            #pragma unroll
            for (int kx = 0; kx < 3; kx++)
                v = fmaf(cW[111 + ky * 3 + kx], sS[(r + ky) * S_W + (c + kx)], v);
        ob[(Y0 + r) * IMG + (X0 + c)] = v;
    }
}

extern "C" void kernel_launch(void* const* d_in, const int* in_sizes, int n_in,
                              void* d_out, int out_size)
{
    const float* img     = (const float*)d_in[0];
    const float* gauss_w = (const float*)d_in[1];
    const float* sobx_w  = (const float*)d_in[2];
    const float* soby_w  = (const float*)d_in[3];
    const float* dir_w   = (const float*)d_in[4];
    const float* nms_w   = (const float*)d_in[5];
    float* out = (float*)d_out;

    prep_weights<<<1, 32>>>(gauss_w, sobx_w, soby_w, dir_w, nms_w);

    void* wptr = nullptr;
    cudaGetSymbolAddress(&wptr, g_wbuf);
    cudaMemcpyToSymbolAsync(cW, wptr, 120 * sizeof(float), 0,
                            cudaMemcpyDeviceToDevice, 0);

    dim3 grid(IMG / TS, IMG / TS, 32);
    canny_main<<<grid, 256>>>(img, out);
}

// round 4
// speedup vs baseline: 1.4677x; 1.1144x over previous
#include <cuda_runtime.h>
#include <cuda_bf16.h>
#include <math.h>

// CannyFilter B=32,C=3,H=W=512.
// Interior blocks (14x14 of 16x16): branch-free 3-stage path
//   blur(3x3) -> sobel-mag(2x 3x3 + sqrt) -> fused DR(5x5)
// with 2D register blocking + float2/float4 vector smem traffic.
// Border blocks: proven masked 4-stage path.
// All weights in __constant__ (FFMA c[][] operands, zero weight loads).

#define IMG 512
#define TS 32
#define I_W 40   // img tile  (halo 4)
#define B_W 38   // blur tile (halo 3)
#define M_W 36   // mag tile  (halo 2)
#define S_W 34   // S tile    (halo 1, border path only)

// cW layout: [0:25) GX (unused), [25:50) GY (unused), [50:75) DR,
//            [75:84) G, [84:93) X, [93:102) Y, [102:111) D, [111:120) R
__constant__ float cW[120];
__device__ float g_wbuf[120];

__global__ void prep_weights(const float* __restrict__ g, const float* __restrict__ sx,
                             const float* __restrict__ sy, const float* __restrict__ dw,
                             const float* __restrict__ nw)
{
    int t = threadIdx.x;
    if (t < 25) {
        int wy = t / 5, wx = t % 5;
        float ax = 0.f, ay = 0.f, ad = 0.f;
        for (int vy = 0; vy < 3; vy++)
            for (int vx = 0; vx < 3; vx++) {
                int uy = wy - vy, ux = wx - vx;
                if (uy >= 0 && uy < 3 && ux >= 0 && ux < 3) {
                    float gg = g[vy * 3 + vx];
                    ax += gg * sx[uy * 3 + ux];
                    ay += gg * sy[uy * 3 + ux];
                    for (int k = 0; k < 8; k++)   // exact dir/nms composition
                        ad += dw[k * 9 + vy * 3 + vx] * nw[k * 9 + uy * 3 + ux];
                }
            }
        g_wbuf[t] = ax; g_wbuf[25 + t] = ay; g_wbuf[50 + t] = ad;
    }
    if (t < 9) {
        g_wbuf[75 + t] = g[t];
        g_wbuf[84 + t] = sx[t];
        g_wbuf[93 + t] = sy[t];
        float d = 0.f;
        for (int k = 0; k < 8; k++) d += dw[k * 9 + t];
        g_wbuf[102 + t] = d;
        g_wbuf[111 + t] = nw[t];
    }
}

__global__ __launch_bounds__(256)
void canny_main(const float* __restrict__ img, float* __restrict__ out)
{
    __shared__ __align__(16) float sI[I_W * I_W];
    __shared__ __align__(16) float sB[B_W * B_W];
    __shared__ __align__(16) float sM[M_W * M_W];
    __shared__ __align__(16) float sS[S_W * S_W];   // border path only

    const int tid = threadIdx.x;
    const int X0 = blockIdx.x * TS, Y0 = blockIdx.y * TS, b = blockIdx.z;
    const float* im = img + (size_t)b * 3 * IMG * IMG;
    float* ob = out + (size_t)b * IMG * IMG;

    const bool interior = (blockIdx.x - 1u < 14u) && (blockIdx.y - 1u < 14u);

    if (interior) {
        // ---- stage 0: 40x40 channel-summed img tile, all float4 ----
        {
            const int base = (Y0 - 4) * IMG + (X0 - 4);      // divisible by 4
            const float4* im4 = (const float4*)(im + base);
            float4* sI4 = (float4*)sI;
            #pragma unroll
            for (int it = 0; it < 2; it++) {
                const int i = tid + it * 256;
                if (i < 400) {
                    const int r = i / 10, c4 = i - r * 10;
                    const int g4 = r * (IMG / 4) + c4;
                    float4 a = __ldg(im4 + g4);
                    float4 b2 = __ldg(im4 + (IMG * IMG / 4) + g4);
                    float4 c = __ldg(im4 + (2 * IMG * IMG / 4) + g4);
                    sI4[i] = make_float4(a.x + b2.x + c.x, a.y + b2.y + c.y,
                                         a.z + b2.z + c.z, a.w + b2.w + c.w);
                }
            }
        }
        __syncthreads();

        // ---- stage 1: blur 38x38, 2 cols x 3 rows per thread ----
        if (tid < 247) {                      // 19 col-groups x 13 row-groups
            const int rg = tid / 19, cg = tid - rg * 19;
            const int c0 = cg * 2, r0 = rg * 3;
            float acc[3][2] = {{0, 0}, {0, 0}, {0, 0}};
            #pragma unroll
            for (int ir = 0; ir < 5; ir++) {
                int rr = r0 + ir; rr = rr < 40 ? rr : 39;   // tail clamp (garbage unused)
                const float2* p = (const float2*)&sI[rr * I_W + c0];
                const float2 u = p[0], w = p[1];
                const float v0 = u.x, v1 = u.y, v2 = w.x, v3 = w.y;
                #pragma unroll
                for (int k = 0; k < 3; k++) {
                    const int ky = ir - k;
                    if (ky >= 0 && ky < 3) {
                        const float g0 = cW[75 + ky * 3], g1 = cW[76 + ky * 3],
                                    g2 = cW[77 + ky * 3];
                        acc[k][0] = fmaf(g0, v0, fmaf(g1, v1, fmaf(g2, v2, acc[k][0])));
                        acc[k][1] = fmaf(g0, v1, fmaf(g1, v2, fmaf(g2, v3, acc[k][1])));
                    }
                }
            }
            #pragma unroll
            for (int k = 0; k < 3; k++)
                if (r0 + k < 38)
                    *(float2*)&sB[(r0 + k) * B_W + c0] = make_float2(acc[k][0], acc[k][1]);
        }
        __syncthreads();

        // ---- stage 2: mag 36x36, 2 cols x 3 rows per thread ----
        if (tid < 216) {                      // 18 x 12, exact
            const int rg = tid / 18, cg = tid - rg * 18;
            const int c0 = cg * 2, r0 = rg * 3;
            float ax[3][2] = {{0, 0}, {0, 0}, {0, 0}};
            float ay[3][2] = {{0, 0}, {0, 0}, {0, 0}};
            #pragma unroll
            for (int ir = 0; ir < 5; ir++) {
                const float2* p = (const float2*)&sB[(r0 + ir) * B_W + c0];
                const float2 u = p[0], w = p[1];
                const float v0 = u.x, v1 = u.y, v2 = w.x, v3 = w.y;
                #pragma unroll
                for (int k = 0; k < 3; k++) {
                    const int ky = ir - k;
                    if (ky >= 0 && ky < 3) {
                        const float x0 = cW[84 + ky * 3], x1 = cW[85 + ky * 3],
                                    x2 = cW[86 + ky * 3];
                        const float y0 = cW[93 + ky * 3], y1 = cW[94 + ky * 3],
                                    y2 = cW[95 + ky * 3];
                        ax[k][0] = fmaf(x0, v0, fmaf(x1, v1, fmaf(x2, v2, ax[k][0])));
                        ax[k][1] = fmaf(x0, v1, fmaf(x1, v2, fmaf(x2, v3, ax[k][1])));
                        ay[k][0] = fmaf(y0, v0, fmaf(y1, v1, fmaf(y2, v2, ay[k][0])));
                        ay[k][1] = fmaf(y0, v1, fmaf(y1, v2, fmaf(y2, v3, ay[k][1])));
                    }
                }
            }
            #pragma unroll
            for (int k = 0; k < 3; k++) {
                const float m0 = sqrtf(ax[k][0] * ax[k][0] + ay[k][0] * ay[k][0]) * (1.f / 3.f);
                const float m1 = sqrtf(ax[k][1] * ax[k][1] + ay[k][1] * ay[k][1]) * (1.f / 3.f);
                *(float2*)&sM[(r0 + k) * M_W + c0] = make_float2(m0, m1);
            }
        }
        __syncthreads();

        // ---- stage 3: out 32x32 via fused 5x5 DR, 2 cols x 2 rows per thread ----
        {
            const int cg = tid & 15, rg = tid >> 4;
            const int c0 = cg * 2, r0 = rg * 2;
            float acc[2][2] = {{0, 0}, {0, 0}};
            #pragma unroll
            for (int ir = 0; ir < 6; ir++) {
                const float2* p = (const float2*)&sM[(r0 + ir) * M_W + c0];
                const float2 u = p[0], w = p[1], z = p[2];
                const float v[6] = {u.x, u.y, w.x, w.y, z.x, z.y};
                #pragma unroll
                for (int k = 0; k < 2; k++) {
                    const int wr = ir - k;
                    if (wr >= 0 && wr < 5) {
                        #pragma unroll
                        for (int j = 0; j < 5; j++) {
                            const float d = cW[50 + wr * 5 + j];
                            acc[k][0] = fmaf(d, v[j], acc[k][0]);
                            acc[k][1] = fmaf(d, v[j + 1], acc[k][1]);
                        }
                    }
                }
            }
            #pragma unroll
            for (int k = 0; k < 2; k++)
                *(float2*)&ob[(Y0 + r0 + k) * IMG + X0 + c0] =
                    make_float2(acc[k][0], acc[k][1]);
        }
        return;
    }

    // ================= border path: masked 4-stage (proven exact) =================
    for (int i = tid; i < I_W * I_W; i += 256) {
        const int r = i / I_W, c = i - r * I_W;
        const int gy = Y0 + r - 4, gx = X0 + c - 4;
        float v = 0.f;
        if ((unsigned)gy < IMG && (unsigned)gx < IMG) {
            const int off = gy * IMG + gx;
            v = __ldg(im + off) + __ldg(im + IMG * IMG + off)
              + __ldg(im + 2 * IMG * IMG + off);
        }
        sI[i] = v;
    }
    __syncthreads();

    for (int i = tid; i < B_W * B_W; i += 256) {
        const int r = i / B_W, c = i - r * B_W;
        const int gy = Y0 + r - 3, gx = X0 + c - 3;
        float v = 0.f;
        if ((unsigned)gy < IMG && (unsigned)gx < IMG) {
            #pragma unroll
            for (int ky = 0; ky < 3; ky++)
                #pragma unroll
                for (int kx = 0; kx < 3; kx++)
                    v = fmaf(cW[75 + ky * 3 + kx], sI[(r + ky) * I_W + (c + kx)], v);
        }
        sB[i] = v;
    }
    __syncthreads();

    for (int i = tid; i < M_W * M_W; i += 256) {
        const int r = i / M_W, c = i - r * M_W;
        const int gy = Y0 + r - 2, gx = X0 + c - 2;
        float v = 0.f;
        if ((unsigned)gy < IMG && (unsigned)gx < IMG) {
            float ax = 0.f, ay = 0.f;
            #pragma unroll
            for (int ky = 0; ky < 3; ky++)
                #pragma unroll
                for (int kx = 0; kx < 3; kx++) {
                    const float t = sB[(r + ky) * B_W + (c + kx)];
                    ax = fmaf(cW[84 + ky * 3 + kx], t, ax);
                    ay = fmaf(cW[93 + ky * 3 + kx], t, ay);
                }
            v = sqrtf(ax * ax + ay * ay) * (1.f / 3.f);
        }
        sM[i] = v;
    }
    __syncthreads();

    for (int i = tid; i < S_W * S_W; i += 256) {
        const int r = i / S_W, c = i - r * S_W;
        const int gy = Y0 + r - 1, gx = X0 + c - 1;
        float v = 0.f;
        if ((unsigned)gy < IMG && (unsigned)gx < IMG) {
            #pragma unroll
            for (int ky = 0; ky < 3; ky++)
                #pragma unroll
                for (int kx = 0; kx < 3; kx++)
                    v = fmaf(cW[102 + ky * 3 + kx], sM[(r + ky) * M_W + (c + kx)], v);
        }
        sS[i] = v;
    }
    __syncthreads();

    for (int i = tid; i < TS * TS; i += 256) {
        const int r = i >> 5, c = i & 31;
        float v = 0.f;
        #pragma unroll
        for (int ky = 0; ky < 3; ky++)
            #pragma unroll
            for (int kx = 0; kx < 3; kx++)
                v = fmaf(cW[111 + ky * 3 + kx], sS[(r + ky) * S_W + (c + kx)], v);
        ob[(Y0 + r) * IMG + (X0 + c)] = v;
    }
}

extern "C" void kernel_launch(void* const* d_in, const int* in_sizes, int n_in,
                              void* d_out, int out_size)
{
    const float* img     = (const float*)d_in[0];
    const float* gauss_w = (const float*)d_in[1];
    const float* sobx_w  = (const float*)d_in[2];
    const float* soby_w  = (const float*)d_in[3];
    const float* dir_w   = (const float*)d_in[4];
    const float* nms_w   = (const float*)d_in[5];
    float* out = (float*)d_out;

    prep_weights<<<1, 32>>>(gauss_w, sobx_w, soby_w, dir_w, nms_w);

    void* wptr = nullptr;
    cudaGetSymbolAddress(&wptr, g_wbuf);
    cudaMemcpyToSymbolAsync(cW, wptr, 120 * sizeof(float), 0,
                            cudaMemcpyDeviceToDevice, 0);

    dim3 grid(IMG / TS, IMG / TS, 32);
    canny_main<<<grid, 256>>>(img, out);
}